// round 4
// baseline (speedup 1.0000x reference)
#include <cuda_runtime.h>
#include <cuda_fp16.h>
#include <cstdint>
#include <math.h>

// ============================================================================
// ChessNNUE fused kernel, sm_103-compatible path (mma.sync fp16 + cp.async).
// tcgen05 unavailable (harness targets compute_103, no 'a' features).
//   prep: fp32 -> fp16 (features, ft_w, l1_w)   [fp16: 8x less quant error
//         than bf16 at identical mma.sync throughput and storage]
//   main: resident-A fused  feat@ft_w^T + ftb -> stm mix -> clip
//         -> l1 via second mma.sync chain -> l2 -> l3 -> sigmoid
// ============================================================================

static constexpr int KDIM = 768;
static constexpr int HID  = 1024;
static constexpr int TILEM = 64;        // batch rows per CTA
static constexpr int NTHREADS = 256;
static constexpr int MAXB = 65536;
static constexpr int KT_PER_CHUNK = 12; // 768 / 64
static constexpr int NCHUNKS = 16;      // 1024 / 64
static constexpr int NTILES = NCHUNKS * KT_PER_CHUNK; // 192

// ---- device scratch (static __device__ arrays: the sanctioned path) ----
__device__ __align__(128) __half g_white_h[(size_t)MAXB * KDIM];
__device__ __align__(128) __half g_black_h[(size_t)MAXB * KDIM];
__device__ __align__(128) __half g_ftw_h[(size_t)HID * KDIM];
__device__ __align__(128) __half g_l1wh[8 * 2 * HID];

// ---- smem layout (byte offsets from 128-aligned base) ----
static constexpr uint32_t A_STRIDE_B = 776 * 2;             // 1552 B/row (pad: bank-safe)
static constexpr uint32_t A_BYTES    = TILEM * A_STRIDE_B;  // 99328
static constexpr uint32_t OFF_AW     = 0;
static constexpr uint32_t OFF_AB     = A_BYTES;             // 99328
static constexpr uint32_t FT_STRIDE  = 72 * 2;              // 144 B/row
static constexpr uint32_t FT_BYTES   = 64 * FT_STRIDE;      // 9216
static constexpr uint32_t OFF_FT     = 2 * A_BYTES;         // 198656
static constexpr uint32_t OFF_FTB    = OFF_FT + 2 * FT_BYTES; // 217088
static constexpr uint32_t OFF_SRED   = OFF_FTB + HID * 4;     // 221184
static constexpr uint32_t SMEM_SPAN  = OFF_SRED + TILEM * 8 * 4; // 223232
static constexpr uint32_t SMEM_DYN   = SMEM_SPAN + 128;

// ---------------------------------------------------------------------------
__device__ __forceinline__ uint32_t smem_u32(const void* p) {
    uint32_t a;
    asm("{ .reg .u64 t; cvta.to.shared.u64 t, %1; cvt.u32.u64 %0, t; }" : "=r"(a) : "l"(p));
    return a;
}
__device__ __forceinline__ void cp16(uint32_t dst, const void* src) {
    asm volatile("cp.async.cg.shared.global [%0], [%1], 16;" :: "r"(dst), "l"(src));
}
#define CP_COMMIT()  asm volatile("cp.async.commit_group;" ::: "memory")
#define CP_WAIT(n)   asm volatile("cp.async.wait_group %0;" :: "n"(n) : "memory")

__device__ __forceinline__ void mma_f16(float c[4], uint32_t a0, uint32_t a1,
                                        uint32_t a2, uint32_t a3,
                                        uint32_t b0, uint32_t b1) {
    asm volatile(
        "mma.sync.aligned.m16n8k16.row.col.f32.f16.f16.f32 "
        "{%0,%1,%2,%3}, {%4,%5,%6,%7}, {%8,%9}, {%0,%1,%2,%3};\n"
        : "+f"(c[0]), "+f"(c[1]), "+f"(c[2]), "+f"(c[3])
        : "r"(a0), "r"(a1), "r"(a2), "r"(a3), "r"(b0), "r"(b1));
}
__device__ __forceinline__ float clip01(float x) {
    return fminf(fmaxf(x, 0.0f), 1.0f);
}
__device__ __forceinline__ uint32_t pack_h2(float lo, float hi) {
    __half2 v = __floats2half2_rn(lo, hi);
    return *reinterpret_cast<uint32_t*>(&v);
}

// ---------------------------------------------------------------------------
// prep: fp32 -> fp16
// ---------------------------------------------------------------------------
__global__ void nnue_prep(const float* __restrict__ wf, const float* __restrict__ bfeat,
                          const float* __restrict__ fw, const float* __restrict__ l1w,
                          int npair_feat) {
    int i0 = blockIdx.x * blockDim.x + threadIdx.x;
    int stride = gridDim.x * blockDim.x;
    __half2* wdst = reinterpret_cast<__half2*>(g_white_h);
    __half2* bdst = reinterpret_cast<__half2*>(g_black_h);
    __half2* fdst = reinterpret_cast<__half2*>(g_ftw_h);
    __half2* ldst = reinterpret_cast<__half2*>(g_l1wh);
    const float2* wsrc = reinterpret_cast<const float2*>(wf);
    const float2* bsrc = reinterpret_cast<const float2*>(bfeat);
    const float2* fsrc = reinterpret_cast<const float2*>(fw);
    const float2* lsrc = reinterpret_cast<const float2*>(l1w);
    for (int j = i0; j < npair_feat; j += stride) {
        float2 a = wsrc[j]; wdst[j] = __floats2half2_rn(a.x, a.y);
        float2 c = bsrc[j]; bdst[j] = __floats2half2_rn(c.x, c.y);
    }
    for (int j = i0; j < HID * KDIM / 2; j += stride) {
        float2 a = fsrc[j]; fdst[j] = __floats2half2_rn(a.x, a.y);
    }
    for (int j = i0; j < 8 * 2 * HID / 2; j += stride) {
        float2 a = lsrc[j]; ldst[j] = __floats2half2_rn(a.x, a.y);
    }
}

// ---------------------------------------------------------------------------
// main fused kernel
// ---------------------------------------------------------------------------
__global__ __launch_bounds__(NTHREADS, 1) void nnue_main(
    const float* __restrict__ stm, const float* __restrict__ ftb,
    const float* __restrict__ l1b, const float* __restrict__ l2w,
    const float* __restrict__ l2b, const float* __restrict__ l3w,
    const float* __restrict__ l3b, float* __restrict__ out, int B) {
    extern __shared__ char smraw[];
    char* smc = smraw + ((128 - (reinterpret_cast<uintptr_t>(smraw) & 127)) & 127);
    const uint32_t sb = smem_u32(smc);

    const int tid = threadIdx.x;
    const int lane = tid & 31;
    const int wid = tid >> 5;
    const int warpM = wid & 3;      // row group: rows warpM*16 .. +15
    const int warpN = wid >> 2;     // col half of 64-chunk: warpN*32 .. +31
    const int row0 = blockIdx.x * TILEM;

    // ---- stage resident A (white/black, 64x768 fp16 each) + ftb + ftw tile0 ----
    for (int i = tid; i < TILEM * 96; i += NTHREADS) {   // 96 x 16B chunks per row
        int r = i / 96, c = i % 96;
        cp16(sb + OFF_AW + r * A_STRIDE_B + c * 16,
             g_white_h + (size_t)(row0 + r) * KDIM + c * 8);
        cp16(sb + OFF_AB + r * A_STRIDE_B + c * 16,
             g_black_h + (size_t)(row0 + r) * KDIM + c * 8);
    }
    cp16(sb + OFF_FTB + tid * 16, ftb + tid * 4);        // 1024 floats = 256 x 16B
#pragma unroll
    for (int p = 0; p < 2; p++) {                        // ftw tile 0 (n0=0,k0=0)
        int i = tid + p * NTHREADS;
        int r = i >> 3, c = i & 7;
        cp16(sb + OFF_FT + r * FT_STRIDE + c * 16, g_ftw_h + (size_t)r * KDIM + c * 8);
    }
    CP_COMMIT();

    float wacc[4][4] = {}, bacc[4][4] = {}, sacc[4] = {};
    const float stm_lo = stm[row0 + warpM * 16 + (lane >> 2)];
    const float stm_hi = stm[row0 + warpM * 16 + (lane >> 2) + 8];

    const uint32_t a_row = sb + (warpM * 16 + (lane >> 2)) * A_STRIDE_B + (lane & 3) * 4;

    for (int t = 0; t < NTILES; t++) {
        const int buf = t & 1;
        if (t + 1 < NTILES) {
            const int nt = t + 1;
            const int n0 = (nt / KT_PER_CHUNK) * 64, k0 = (nt % KT_PER_CHUNK) * 64;
#pragma unroll
            for (int p = 0; p < 2; p++) {
                int i = tid + p * NTHREADS;
                int r = i >> 3, c = i & 7;
                cp16(sb + OFF_FT + (nt & 1) * FT_BYTES + r * FT_STRIDE + c * 16,
                     g_ftw_h + (size_t)(n0 + r) * KDIM + k0 + c * 8);
            }
            CP_COMMIT();
            CP_WAIT(1);
        } else {
            CP_WAIT(0);
        }
        __syncthreads();

        const uint32_t ftile = sb + OFF_FT + buf * FT_BYTES;
        const int k0 = (t % KT_PER_CHUNK) * 64;
#pragma unroll
        for (int ks = 0; ks < 4; ks++) {
            const uint32_t ka = a_row + (uint32_t)(k0 + ks * 16) * 2 + OFF_AW;
            const char* pw = smc + (ka - sb);
            const char* pb = pw + (OFF_AB - OFF_AW);
            uint32_t aw0 = *(const uint32_t*)(pw);
            uint32_t aw1 = *(const uint32_t*)(pw + 8 * A_STRIDE_B);
            uint32_t aw2 = *(const uint32_t*)(pw + 16);
            uint32_t aw3 = *(const uint32_t*)(pw + 8 * A_STRIDE_B + 16);
            uint32_t ab0 = *(const uint32_t*)(pb);
            uint32_t ab1 = *(const uint32_t*)(pb + 8 * A_STRIDE_B);
            uint32_t ab2 = *(const uint32_t*)(pb + 16);
            uint32_t ab3 = *(const uint32_t*)(pb + 8 * A_STRIDE_B + 16);
#pragma unroll
            for (int b = 0; b < 4; b++) {
                const int n = warpN * 32 + b * 8 + (lane >> 2);
                const char* pf = smc + (ftile - sb) + n * FT_STRIDE +
                                 (ks * 16 + (lane & 3) * 2) * 2;
                uint32_t b0 = *(const uint32_t*)(pf);
                uint32_t b1 = *(const uint32_t*)(pf + 16);
                mma_f16(wacc[b], aw0, aw1, aw2, aw3, b0, b1);
                mma_f16(bacc[b], ab0, ab1, ab2, ab3, b0, b1);
            }
        }
        __syncthreads();

        // ---- per-chunk epilogue: +ftb, mix, clip, l1 via mma ----
        if ((t % KT_PER_CHUNK) == KT_PER_CHUNK - 1) {
            const int chunk = t / KT_PER_CHUNK;
#pragma unroll
            for (int kg = 0; kg < 2; kg++) {
                uint32_t A1[4], A2[4];
#pragma unroll
                for (int h = 0; h < 2; h++) {
                    const int b = kg * 2 + h;
                    const int nidx = chunk * 64 + warpN * 32 + b * 8 + 2 * (lane & 3);
                    const float2 fb = *(const float2*)(smc + OFF_FTB + nidx * 4);
                    float a1v[4], a2v[4];
#pragma unroll
                    for (int j = 0; j < 4; j++) {
                        const float fbv = (j & 1) ? fb.y : fb.x;
                        const float sv = (j < 2) ? stm_lo : stm_hi;
                        const float wv = wacc[b][j] + fbv;
                        const float bv = bacc[b][j] + fbv;
                        a1v[j] = clip01(sv * wv + (1.0f - sv) * bv);
                        a2v[j] = clip01(sv * bv + (1.0f - sv) * wv);
                    }
                    A1[h * 2 + 0] = pack_h2(a1v[0], a1v[1]);
                    A1[h * 2 + 1] = pack_h2(a1v[2], a1v[3]);
                    A2[h * 2 + 0] = pack_h2(a2v[0], a2v[1]);
                    A2[h * 2 + 1] = pack_h2(a2v[2], a2v[3]);
                    // reset accumulators for next chunk
                    wacc[b][0] = wacc[b][1] = wacc[b][2] = wacc[b][3] = 0.0f;
                    bacc[b][0] = bacc[b][1] = bacc[b][2] = bacc[b][3] = 0.0f;
                }
                // fragment order: a0=lo/klo a1=hi/klo a2=lo/khi a3=hi/khi
                const uint32_t Aa[4] = {A1[0], A1[1], A1[2], A1[3]};
                const uint32_t Ab2[4] = {A2[0], A2[1], A2[2], A2[3]};
                const int kcol = chunk * 64 + warpN * 32 + kg * 16 + 2 * (lane & 3);
                const __half* bp = g_l1wh + (size_t)(lane >> 2) * (2 * HID) + kcol;
                uint32_t B10 = *(const uint32_t*)(bp);
                uint32_t B11 = *(const uint32_t*)(bp + 8);
                uint32_t B20 = *(const uint32_t*)(bp + HID);
                uint32_t B21 = *(const uint32_t*)(bp + HID + 8);
                mma_f16(sacc, Aa[0], Aa[1], Aa[2], Aa[3], B10, B11);
                mma_f16(sacc, Ab2[0], Ab2[1], Ab2[2], Ab2[3], B20, B21);
            }
        }
    }

    // ---- reduce l1 partials across warpN pairs, then tiny head ----
    float* sred = reinterpret_cast<float*>(smc + OFF_SRED);
    const int rlo = warpM * 16 + (lane >> 2);
    const int rhi = rlo + 8;
    const int o0 = 2 * (lane & 3);
    __syncthreads();
    if (warpN == 0) {
        sred[rlo * 8 + o0] = sacc[0];
        sred[rlo * 8 + o0 + 1] = sacc[1];
        sred[rhi * 8 + o0] = sacc[2];
        sred[rhi * 8 + o0 + 1] = sacc[3];
    }
    __syncthreads();
    if (warpN == 1) {
        sred[rlo * 8 + o0] += sacc[0];
        sred[rlo * 8 + o0 + 1] += sacc[1];
        sred[rhi * 8 + o0] += sacc[2];
        sred[rhi * 8 + o0 + 1] += sacc[3];
    }
    __syncthreads();

    if (tid < TILEM) {
        const int gr = row0 + tid;
        float l2x[8];
#pragma unroll
        for (int o = 0; o < 8; o++)
            l2x[o] = clip01(sred[tid * 8 + o] + __ldg(&l1b[o]));
        float rawv = __ldg(&l3b[0]);
#pragma unroll
        for (int j = 0; j < 32; j++) {
            float tacc = __ldg(&l2b[j]);
#pragma unroll
            for (int o = 0; o < 8; o++) tacc += __ldg(&l2w[j * 8 + o]) * l2x[o];
            rawv += __ldg(&l3w[j]) * clip01(tacc);
        }
        out[gr] = 1.0f / (1.0f + expf(-rawv));
        out[B + gr] = rawv;
    }
}

// ---------------------------------------------------------------------------
// launch
// ---------------------------------------------------------------------------
extern "C" void kernel_launch(void* const* d_in, const int* in_sizes, int n_in,
                              void* d_out, int out_size) {
    const float* white = (const float*)d_in[0];
    const float* black = (const float*)d_in[1];
    const float* stm   = (const float*)d_in[2];
    const float* ftw   = (const float*)d_in[3];
    const float* ftb   = (const float*)d_in[4];
    const float* l1w   = (const float*)d_in[5];
    const float* l1b   = (const float*)d_in[6];
    const float* l2w   = (const float*)d_in[7];
    const float* l2b   = (const float*)d_in[8];
    const float* l3w   = (const float*)d_in[9];
    const float* l3b   = (const float*)d_in[10];
    float* out = (float*)d_out;

    const int B = in_sizes[2];  // stm element count

    nnue_prep<<<2048, 256>>>(white, black, ftw, l1w, B * KDIM / 2);

    static int configured = 0;
    if (!configured) {
        cudaFuncSetAttribute(nnue_main, cudaFuncAttributeMaxDynamicSharedMemorySize,
                             SMEM_DYN);
        configured = 1;
    }
    nnue_main<<<B / TILEM, NTHREADS, SMEM_DYN>>>(stm, ftb, l1b, l2w, l2b, l3w, l3b,
                                                 out, B);
}